// round 6
// baseline (speedup 1.0000x reference)
#include <cuda_runtime.h>

typedef unsigned int u32;
typedef unsigned short u16;

#define BB 4
#define SS 4096
#define DIN 1024
#define DH 64
#define MROWS (BB*SS)
#define NSPLIT 2
#define KTS (SS/64)
#define KT_PER (KTS/NSPLIT)

// stage geometry (bytes): one array = 64 rows x 72 u16 = 9216 B; 4 arrays/stage
#define ARR_B   9216
#define STAGE_B 36864

// ---------------- scratch (static device memory; no allocations) ----------
__device__ u16 g_Xh[MROWS*DIN], g_Xl[MROWS*DIN];           // X split bf16
__device__ u16 g_Wth[3][DH*DIN], g_Wtl[3][DH*DIN];         // W^T split bf16 [out][din]
__device__ u16 g_Qh[MROWS*DH], g_Ql[MROWS*DH];             // [row][d]
__device__ u16 g_Kh[MROWS*DH], g_Kl[MROWS*DH];             // [row][d]
__device__ u16 g_Vh[MROWS*DH], g_Vl[MROWS*DH];             // transposed [b][d][s]
__device__ float g_Op[NSPLIT][MROWS*DH];                   // unnormalized partial O
__device__ float g_m[NSPLIT][MROWS];
__device__ float g_l[NSPLIT][MROWS];

// ---------------- helpers --------------------------------------------------
__device__ __forceinline__ u32 packbf(float lo, float hi){
    u32 r; asm("cvt.rn.bf16x2.f32 %0, %1, %2;" : "=r"(r) : "f"(hi), "f"(lo)); return r;
}
__device__ __forceinline__ float bflo(u32 p){ return __uint_as_float(p << 16); }
__device__ __forceinline__ float bfhi(u32 p){ return __uint_as_float(p & 0xffff0000u); }
__device__ __forceinline__ u32 smaddr(const void* p){ return (u32)__cvta_generic_to_shared(p); }

__device__ __forceinline__ void ldsm4(u32& r0,u32& r1,u32& r2,u32& r3, u32 a){
    asm volatile("ldmatrix.sync.aligned.m8n8.x4.shared.b16 {%0,%1,%2,%3}, [%4];"
        : "=r"(r0),"=r"(r1),"=r"(r2),"=r"(r3) : "r"(a));
}
// NOTE: not volatile — register-only op; lets ptxas software-pipeline chains.
__device__ __forceinline__ void mma_bf(float* c, const u32* a, u32 b0, u32 b1){
    asm("mma.sync.aligned.m16n8k16.row.col.f32.bf16.bf16.f32 "
        "{%0,%1,%2,%3},{%4,%5,%6,%7},{%8,%9},{%0,%1,%2,%3};"
        : "+f"(c[0]),"+f"(c[1]),"+f"(c[2]),"+f"(c[3])
        : "r"(a[0]),"r"(a[1]),"r"(a[2]),"r"(a[3]),"r"(b0),"r"(b1));
}
__device__ __forceinline__ void cpa16(u32 dst, const void* src){
    asm volatile("cp.async.cg.shared.global [%0], [%1], 16;" :: "r"(dst), "l"(src));
}
#define CP_COMMIT() asm volatile("cp.async.commit_group;")
#define CP_WAIT1()  asm volatile("cp.async.wait_group 1;")

// ---------------- kernel: convert X to split bf16 --------------------------
__global__ __launch_bounds__(256) void cvt_x(const float* __restrict__ X){
    size_t i = (size_t)(blockIdx.x*256 + threadIdx.x) * 4;
    float4 v = *(const float4*)&X[i];
    u32 h01 = packbf(v.x, v.y), h23 = packbf(v.z, v.w);
    u32 l01 = packbf(v.x - bflo(h01), v.y - bfhi(h01));
    u32 l23 = packbf(v.z - bflo(h23), v.w - bfhi(h23));
    *(uint2*)&g_Xh[i] = make_uint2(h01, h23);
    *(uint2*)&g_Xl[i] = make_uint2(l01, l23);
}

// ---------------- kernel: convert+transpose weights ------------------------
__global__ __launch_bounds__(256) void cvt_w(const float* __restrict__ Wq,
                                             const float* __restrict__ Wk,
                                             const float* __restrict__ Wv){
    int id = blockIdx.x*256 + threadIdx.x;     // 3 * 64 * 1024
    int w = id >> 16; int r = id & 65535;
    int n = r >> 10, k = r & 1023;
    const float* W = (w==0) ? Wq : (w==1) ? Wk : Wv;
    float x = W[k*DH + n];
    u32 p = packbf(x, 0.f);
    u32 q = packbf(x - bflo(p), 0.f);
    g_Wth[w][n*DIN + k] = (u16)(p & 0xffff);
    g_Wtl[w][n*DIN + k] = (u16)(q & 0xffff);
}

__device__ __forceinline__ void storeV(int r, int c, float v){
    int bb = r >> 12, s = r & 4095;
    u32 p = packbf(v, 0.f);
    g_Vh[(size_t)(bb*64 + c)*SS + s] = (u16)(p & 0xffff);
    u32 q = packbf(v - bflo(p), 0.f);
    g_Vl[(size_t)(bb*64 + c)*SS + s] = (u16)(q & 0xffff);
}

// ---------------- kernel: QKV projection via MMA, cp.async 2-stage ---------
// grid (MROWS/64, 3), 128 threads. Stage = [Xh|Xl|Wh|Wl] each 64x72 u16.
__global__ __launch_bounds__(128, 3) void qkv_mma(
    const float* __restrict__ bq, const float* __restrict__ bk,
    const float* __restrict__ bv)
{
    extern __shared__ u16 smq[];               // 2 stages x STAGE_B bytes
    const int t = threadIdx.x, lane = t & 31, warp = t >> 5;
    const int w = blockIdx.y;
    const int m0 = blockIdx.x * 64;
    const u16* Wth = g_Wth[w]; const u16* Wtl = g_Wtl[w];
    const float* bias = (w==0) ? bq : (w==1) ? bk : bv;

    const int row = t >> 1, q4h = (t & 1) * 4;     // 4 chunks of 16B per thread per array

    // issue stage for k-chunk cc into stage s (full 64x64 u16 per array)
    auto issue = [&](int cc, int s){
        u32 st = smaddr(smq) + s * STAGE_B;
        #pragma unroll
        for (int h = 0; h < 4; h++){
            int q4 = q4h + h;
            u32 d = st + (row*72 + q4*8) * 2;
            size_t gx = (size_t)(m0+row)*DIN + cc*64 + q4*8;
            size_t gw = (size_t)row*DIN + cc*64 + q4*8;
            cpa16(d,           &g_Xh[gx]);
            cpa16(d +   ARR_B, &g_Xl[gx]);
            cpa16(d + 2*ARR_B, &Wth[gw]);
            cpa16(d + 3*ARR_B, &Wtl[gw]);
        }
    };

    const u32 aoff = ((16*warp + (lane&15))*72 + ((lane>>4)<<3)) * 2;
    const u32 boff = (((lane&7) + ((lane>>4)<<3))*72 + (((lane>>3)&1)<<3)) * 2;

    issue(0, 0); CP_COMMIT();
    issue(1, 1); CP_COMMIT();

    float acc[8][4] = {};
    for (int c16 = 0; c16 < 16; c16++){
        CP_WAIT1();
        __syncthreads();
        const int s = c16 & 1;
        const u32 st = smaddr(smq) + s * STAGE_B;
        const u32 a_h = st + aoff,             a_l = st + ARR_B + aoff;
        const u32 b_h = st + 2*ARR_B + boff,   b_l = st + 3*ARR_B + boff;
        #pragma unroll
        for (int ks = 0; ks < 4; ks++){
            u32 ah[4], al[4];
            ldsm4(ah[0],ah[1],ah[2],ah[3], a_h + ks*32);
            ldsm4(al[0],al[1],al[2],al[3], a_l + ks*32);
            #pragma unroll
            for (int p = 0; p < 4; p++){
                u32 bh[4], bl[4];
                ldsm4(bh[0],bh[1],bh[2],bh[3], b_h + p*2304 + ks*32);
                ldsm4(bl[0],bl[1],bl[2],bl[3], b_l + p*2304 + ks*32);
                mma_bf(acc[2*p],   ah, bh[0], bh[1]);
                mma_bf(acc[2*p+1], ah, bh[2], bh[3]);
                mma_bf(acc[2*p],   ah, bl[0], bl[1]);
                mma_bf(acc[2*p+1], ah, bl[2], bl[3]);
                mma_bf(acc[2*p],   al, bh[0], bh[1]);
                mma_bf(acc[2*p+1], al, bh[2], bh[3]);
            }
        }
        __syncthreads();
        if (c16 + 2 < 16) issue(c16 + 2, s);
        CP_COMMIT();
    }

    const int g = lane >> 2, t2 = lane & 3;
    const int r0 = m0 + 16*warp + g, r1 = r0 + 8;
    #pragma unroll
    for (int nb = 0; nb < 8; nb++){
        int col = nb*8 + t2*2;
        float b0v = bias[col], b1v = bias[col+1];
        float v00 = fmaxf(acc[nb][0] + b0v, 0.f);
        float v01 = fmaxf(acc[nb][1] + b1v, 0.f);
        float v10 = fmaxf(acc[nb][2] + b0v, 0.f);
        float v11 = fmaxf(acc[nb][3] + b1v, 0.f);
        if (w == 2){
            storeV(r0, col, v00); storeV(r0, col+1, v01);
            storeV(r1, col, v10); storeV(r1, col+1, v11);
        } else {
            u16* Oh = (w==0) ? g_Qh : g_Kh;
            u16* Ol = (w==0) ? g_Ql : g_Kl;
            u32 h = packbf(v00, v01);
            u32 lo = packbf(v00 - bflo(h), v01 - bfhi(h));
            *(u32*)&Oh[(size_t)r0*DH + col] = h; *(u32*)&Ol[(size_t)r0*DH + col] = lo;
            h = packbf(v10, v11);
            lo = packbf(v10 - bflo(h), v11 - bfhi(h));
            *(u32*)&Oh[(size_t)r1*DH + col] = h; *(u32*)&Ol[(size_t)r1*DH + col] = lo;
        }
    }
}

// ---------------- kernel: flash attention via MMA, cp.async 2-stage --------
// grid (SS/64, BB, NSPLIT), 128 threads. Stage = [Kh|Kl|Vh|Vl] each 64x72 u16.
__global__ __launch_bounds__(128, 3) void attn_mma()
{
    extern __shared__ u16 smu[];               // 2 stages x STAGE_B bytes
    const int t = threadIdx.x, lane = t & 31, warp = t >> 5;
    const int b = blockIdx.y, z = blockIdx.z;
    const int q0 = blockIdx.x * 64;
    const int base = b * SS;

    const u32 aoff = ((16*warp + (lane&15))*72 + ((lane>>4)<<3)) * 2;
    const u32 boff = (((lane&7) + ((lane>>4)<<3))*72 + (((lane>>3)&1)<<3)) * 2;

    // ---- prologue: stage Q into stage-0 area, hoist frags to registers ----
    #pragma unroll
    for (int u = 0; u < 4; u++){
        int idx = t + 128*u; int r = idx >> 3, q4 = idx & 7;
        *(uint4*)&smu[r*72 + q4*8]        = *(const uint4*)&g_Qh[(size_t)(base+q0+r)*DH + q4*8];
        *(uint4*)&smu[4608 + r*72 + q4*8] = *(const uint4*)&g_Ql[(size_t)(base+q0+r)*DH + q4*8];
    }
    __syncthreads();
    u32 qh[4][4], ql[4][4];
    {
        const u32 qa = smaddr(smu) + aoff;
        #pragma unroll
        for (int ks = 0; ks < 4; ks++){
            ldsm4(qh[ks][0],qh[ks][1],qh[ks][2],qh[ks][3], qa + ks*32);
            ldsm4(ql[ks][0],ql[ks][1],ql[ks][2],ql[ks][3], qa + ARR_B + ks*32);
        }
    }
    __syncthreads();   // all warps have Q frags; stage-0 reusable

    const int row = t >> 1, q4h = (t & 1) * 4;
    auto issue = [&](int it, int s){
        const int k0 = (z*KT_PER + it) * 64;
        u32 st = smaddr(smu) + s * STAGE_B;
        #pragma unroll
        for (int h = 0; h < 4; h++){
            int q4 = q4h + h;
            u32 d = st + (row*72 + q4*8) * 2;
            size_t gk = (size_t)(base+k0+row)*DH + q4*8;
            size_t gv = (size_t)(b*64+row)*SS + k0 + q4*8;
            cpa16(d,           &g_Kh[gk]);
            cpa16(d +   ARR_B, &g_Kl[gk]);
            cpa16(d + 2*ARR_B, &g_Vh[gv]);
            cpa16(d + 3*ARR_B, &g_Vl[gv]);
        }
    };

    issue(0, 0); CP_COMMIT();
    issue(1, 1); CP_COMMIT();

    float o[8][4] = {};
    float mr[2] = {-3e38f, -3e38f};
    float lr[2] = {0.f, 0.f};

    for (int it = 0; it < KT_PER; it++){
        CP_WAIT1();
        __syncthreads();
        const int stg = it & 1;
        const u32 st = smaddr(smu) + stg * STAGE_B;
        const u32 kh_b = st + boff,             kl_b = st + ARR_B + boff;
        const u32 vh_b = st + 2*ARR_B + boff,   vl_b = st + 3*ARR_B + boff;

        // ---- S = Q @ K^T (split), interleaved accumulator chains ----
        float s[8][4] = {};
        #pragma unroll
        for (int ks = 0; ks < 4; ks++){
            #pragma unroll
            for (int p = 0; p < 4; p++){
                u32 bh[4], bl[4];
                ldsm4(bh[0],bh[1],bh[2],bh[3], kh_b + p*2304 + ks*32);
                ldsm4(bl[0],bl[1],bl[2],bl[3], kl_b + p*2304 + ks*32);
                mma_bf(s[2*p],   qh[ks], bh[0], bh[1]);
                mma_bf(s[2*p+1], qh[ks], bh[2], bh[3]);
                mma_bf(s[2*p],   qh[ks], bl[0], bl[1]);
                mma_bf(s[2*p+1], qh[ks], bl[2], bl[3]);
                mma_bf(s[2*p],   ql[ks], bh[0], bh[1]);
                mma_bf(s[2*p+1], ql[ks], bh[2], bh[3]);
            }
        }

        // ---- online softmax (rows g, g+8), quad-lane reductions ----
        #pragma unroll
        for (int ri = 0; ri < 2; ri++){
            float mi = -3e38f;
            #pragma unroll
            for (int nb = 0; nb < 8; nb++)
                mi = fmaxf(mi, fmaxf(s[nb][2*ri], s[nb][2*ri+1]));
            mi = fmaxf(mi, __shfl_xor_sync(0xffffffffu, mi, 1));
            mi = fmaxf(mi, __shfl_xor_sync(0xffffffffu, mi, 2));
            float mnew = fmaxf(mr[ri], mi);
            float scl = __expf(mr[ri] - mnew);
            mr[ri] = mnew;
            float li = 0.f;
            #pragma unroll
            for (int nb = 0; nb < 8; nb++){
                float e0 = __expf(s[nb][2*ri]   - mnew);
                float e1 = __expf(s[nb][2*ri+1] - mnew);
                s[nb][2*ri] = e0; s[nb][2*ri+1] = e1;
                li += e0 + e1;
                o[nb][2*ri]   *= scl;
                o[nb][2*ri+1] *= scl;
            }
            li += __shfl_xor_sync(0xffffffffu, li, 1);
            li += __shfl_xor_sync(0xffffffffu, li, 2);
            lr[ri] = lr[ri]*scl + li;
        }

        // ---- P C-frag -> A-frag in registers (no shuffles), split ----
        u32 ph[4][4], pl[4][4];
        #pragma unroll
        for (int ks = 0; ks < 4; ks++){
            ph[ks][0] = packbf(s[2*ks][0],   s[2*ks][1]);
            ph[ks][1] = packbf(s[2*ks][2],   s[2*ks][3]);
            ph[ks][2] = packbf(s[2*ks+1][0], s[2*ks+1][1]);
            ph[ks][3] = packbf(s[2*ks+1][2], s[2*ks+1][3]);
            pl[ks][0] = packbf(s[2*ks][0]   - bflo(ph[ks][0]), s[2*ks][1]   - bfhi(ph[ks][0]));
            pl[ks][1] = packbf(s[2*ks][2]   - bflo(ph[ks][1]), s[2*ks][3]   - bfhi(ph[ks][1]));
            pl[ks][2] = packbf(s[2*ks+1][0] - bflo(ph[ks][2]), s[2*ks+1][1] - bfhi(ph[ks][2]));
            pl[ks][3] = packbf(s[2*ks+1][2] - bflo(ph[ks][3]), s[2*ks+1][3] - bfhi(ph[ks][3]));
        }

        // ---- O += P @ V (split), interleaved ----
        #pragma unroll
        for (int ks = 0; ks < 4; ks++){
            #pragma unroll
            for (int p = 0; p < 4; p++){
                u32 vh4[4], vl4[4];
                ldsm4(vh4[0],vh4[1],vh4[2],vh4[3], vh_b + p*2304 + ks*32);
                ldsm4(vl4[0],vl4[1],vl4[2],vl4[3], vl_b + p*2304 + ks*32);
                mma_bf(o[2*p],   ph[ks], vh4[0], vh4[1]);
                mma_bf(o[2*p+1], ph[ks], vh4[2], vh4[3]);
                mma_bf(o[2*p],   ph[ks], vl4[0], vl4[1]);
                mma_bf(o[2*p+1], ph[ks], vl4[2], vl4[3]);
                mma_bf(o[2*p],   pl[ks], vh4[0], vh4[1]);
                mma_bf(o[2*p+1], pl[ks], vh4[2], vh4[3]);
            }
        }

        __syncthreads();
        if (it + 2 < KT_PER) issue(it + 2, stg);
        CP_COMMIT();
    }

    // write unnormalized partials + stats
    const int g = lane >> 2, t2 = lane & 3;
    const int r0 = base + q0 + 16*warp + g, r1 = r0 + 8;
    #pragma unroll
    for (int nb = 0; nb < 8; nb++){
        *(float2*)&g_Op[z][(size_t)r0*DH + nb*8 + t2*2] = make_float2(o[nb][0], o[nb][1]);
        *(float2*)&g_Op[z][(size_t)r1*DH + nb*8 + t2*2] = make_float2(o[nb][2], o[nb][3]);
    }
    if (t2 == 0){
        g_m[z][r0] = mr[0]; g_l[z][r0] = lr[0];
        g_m[z][r1] = mr[1]; g_l[z][r1] = lr[1];
    }
}

// ---------------- kernel: flash split combine + mask -----------------------
__global__ __launch_bounds__(256) void combine(const float* __restrict__ mask,
                                               float* __restrict__ out){
    int idx = blockIdx.x*256 + threadIdx.x;   // row*16 + dquad
    int row = idx >> 4, dq = idx & 15;
    float m0 = g_m[0][row], m1 = g_m[1][row];
    float l0 = g_l[0][row], l1 = g_l[1][row];
    float mm = fmaxf(m0, m1);
    float w0 = __expf(m0 - mm), w1 = __expf(m1 - mm);
    float f = mask[row] / (w0*l0 + w1*l1);
    float4 a = *(const float4*)&g_Op[0][(size_t)row*DH + dq*4];
    float4 c = *(const float4*)&g_Op[1][(size_t)row*DH + dq*4];
    float4 r;
    r.x = (a.x*w0 + c.x*w1) * f;
    r.y = (a.y*w0 + c.y*w1) * f;
    r.z = (a.z*w0 + c.z*w1) * f;
    r.w = (a.w*w0 + c.w*w1) * f;
    *(float4*)&out[(size_t)row*DH + dq*4] = r;
}

// ---------------------------------------------------------------------------
extern "C" void kernel_launch(void* const* d_in, const int* in_sizes, int n_in,
                              void* d_out, int out_size)
{
    const float* X    = (const float*)d_in[0];
    const float* mask = (const float*)d_in[1];
    const float* Wq   = (const float*)d_in[2];
    const float* bq   = (const float*)d_in[3];
    const float* Wk   = (const float*)d_in[4];
    const float* bk   = (const float*)d_in[5];
    const float* Wv   = (const float*)d_in[6];
    const float* bv   = (const float*)d_in[7];

    const int smem_pipe = 2 * STAGE_B;   // 73728 B
    cudaFuncSetAttribute(attn_mma,
                         cudaFuncAttributeMaxDynamicSharedMemorySize, smem_pipe);
    cudaFuncSetAttribute(qkv_mma,
                         cudaFuncAttributeMaxDynamicSharedMemorySize, smem_pipe);

    cvt_x<<<MROWS*DIN/4/256, 256>>>(X);
    cvt_w<<<3*DH*DIN/256, 256>>>(Wq, Wk, Wv);
    qkv_mma<<<dim3(MROWS/64, 3), 128, smem_pipe>>>(bq, bk, bv);
    attn_mma<<<dim3(SS/64, BB, NSPLIT), 128, smem_pipe>>>();
    combine<<<MROWS*DH/4/256, 256>>>(mask, (float*)d_out);
}

// round 7
// speedup vs baseline: 1.3087x; 1.3087x over previous
#include <cuda_runtime.h>

typedef unsigned int u32;
typedef unsigned short u16;

#define BB 4
#define SS 4096
#define DIN 1024
#define DH 64
#define MROWS (BB*SS)
#define NSPLIT 4
#define KTS (SS/64)
#define KT_PER (KTS/NSPLIT)

// ---------------- scratch (static device memory; no allocations) ----------
__device__ u16 g_Xh[MROWS*DIN], g_Xl[MROWS*DIN];           // X split bf16
__device__ u16 g_Wth[3][DH*DIN], g_Wtl[3][DH*DIN];         // W^T split bf16 [out][din]
__device__ u16 g_Qh[MROWS*DH], g_Ql[MROWS*DH];             // [row][d]
__device__ u16 g_Kh[MROWS*DH], g_Kl[MROWS*DH];             // [row][d]
__device__ u16 g_Vh[MROWS*DH], g_Vl[MROWS*DH];             // transposed [b][d][s]
__device__ float g_Op[NSPLIT][MROWS*DH];                   // unnormalized partial O
__device__ float g_m[NSPLIT][MROWS];
__device__ float g_l[NSPLIT][MROWS];

// ---------------- helpers --------------------------------------------------
__device__ __forceinline__ u32 packbf(float lo, float hi){
    u32 r; asm("cvt.rn.bf16x2.f32 %0, %1, %2;" : "=r"(r) : "f"(hi), "f"(lo)); return r;
}
__device__ __forceinline__ float bflo(u32 p){ return __uint_as_float(p << 16); }
__device__ __forceinline__ float bfhi(u32 p){ return __uint_as_float(p & 0xffff0000u); }
__device__ __forceinline__ u32 smaddr(const void* p){ return (u32)__cvta_generic_to_shared(p); }

__device__ __forceinline__ void ldsm4(u32& r0,u32& r1,u32& r2,u32& r3, u32 a){
    asm volatile("ldmatrix.sync.aligned.m8n8.x4.shared.b16 {%0,%1,%2,%3}, [%4];"
        : "=r"(r0),"=r"(r1),"=r"(r2),"=r"(r3) : "r"(a));
}
__device__ __forceinline__ void mma_bf(float* c, const u32* a, u32 b0, u32 b1){
    asm volatile("mma.sync.aligned.m16n8k16.row.col.f32.bf16.bf16.f32 "
        "{%0,%1,%2,%3},{%4,%5,%6,%7},{%8,%9},{%0,%1,%2,%3};"
        : "+f"(c[0]),"+f"(c[1]),"+f"(c[2]),"+f"(c[3])
        : "r"(a[0]),"r"(a[1]),"r"(a[2]),"r"(a[3]),"r"(b0),"r"(b1));
}

// ---------------- kernel: convert X to split bf16 --------------------------
__global__ __launch_bounds__(256) void cvt_x(const float* __restrict__ X){
    size_t i = (size_t)(blockIdx.x*256 + threadIdx.x) * 4;
    float4 v = *(const float4*)&X[i];
    u32 h01 = packbf(v.x, v.y), h23 = packbf(v.z, v.w);
    u32 l01 = packbf(v.x - bflo(h01), v.y - bfhi(h01));
    u32 l23 = packbf(v.z - bflo(h23), v.w - bfhi(h23));
    *(uint2*)&g_Xh[i] = make_uint2(h01, h23);
    *(uint2*)&g_Xl[i] = make_uint2(l01, l23);
}

// ---------------- kernel: convert+transpose weights ------------------------
__global__ __launch_bounds__(256) void cvt_w(const float* __restrict__ Wq,
                                             const float* __restrict__ Wk,
                                             const float* __restrict__ Wv){
    int id = blockIdx.x*256 + threadIdx.x;     // 3 * 64 * 1024
    int w = id >> 16; int r = id & 65535;
    int n = r >> 10, k = r & 1023;
    const float* W = (w==0) ? Wq : (w==1) ? Wk : Wv;
    float x = W[k*DH + n];
    u32 p = packbf(x, 0.f);
    u32 q = packbf(x - bflo(p), 0.f);
    g_Wth[w][n*DIN + k] = (u16)(p & 0xffff);
    g_Wtl[w][n*DIN + k] = (u16)(q & 0xffff);
}

__device__ __forceinline__ void storeV(int r, int c, float v){
    int bb = r >> 12, s = r & 4095;
    u32 p = packbf(v, 0.f);
    g_Vh[(size_t)(bb*64 + c)*SS + s] = (u16)(p & 0xffff);
    u32 q = packbf(v - bflo(p), 0.f);
    g_Vl[(size_t)(bb*64 + c)*SS + s] = (u16)(q & 0xffff);
}

// ---------------- kernel: QKV projection via MMA ---------------------------
// grid (MROWS/64, 3), 128 threads (4 warps x 16 rows). out = relu(X@W + b).
__global__ __launch_bounds__(128, 4) void qkv_mma(
    const float* __restrict__ bq, const float* __restrict__ bk,
    const float* __restrict__ bv)
{
    __shared__ u16 Xs_h[64*72], Xs_l[64*72], Ws_h[64*72], Ws_l[64*72];
    const int t = threadIdx.x, lane = t & 31, warp = t >> 5;
    const int w = blockIdx.y;
    const int m0 = blockIdx.x * 64;
    const u16* Wth = g_Wth[w]; const u16* Wtl = g_Wtl[w];
    const float* bias = (w==0) ? bq : (w==1) ? bk : bv;

    const u32 aoff = ((16*warp + (lane&15))*72 + ((lane>>4)<<3)) * 2;
    const u32 boff = (((lane&7) + ((lane>>4)<<3))*72 + (((lane>>3)&1)<<3)) * 2;
    const u32 a_h = smaddr(Xs_h) + aoff, a_l = smaddr(Xs_l) + aoff;
    const u32 b_h = smaddr(Ws_h) + boff, b_l = smaddr(Ws_l) + boff;

    float acc[8][4] = {};
    for (int c16 = 0; c16 < 16; c16++){
        __syncthreads();
        #pragma unroll
        for (int u = 0; u < 4; u++){
            int idx = t + 128*u; int row = idx >> 3, q4 = idx & 7;
            *(uint4*)&Xs_h[row*72 + q4*8] = *(const uint4*)&g_Xh[(size_t)(m0+row)*DIN + c16*64 + q4*8];
            *(uint4*)&Xs_l[row*72 + q4*8] = *(const uint4*)&g_Xl[(size_t)(m0+row)*DIN + c16*64 + q4*8];
            *(uint4*)&Ws_h[row*72 + q4*8] = *(const uint4*)&Wth[(size_t)row*DIN + c16*64 + q4*8];
            *(uint4*)&Ws_l[row*72 + q4*8] = *(const uint4*)&Wtl[(size_t)row*DIN + c16*64 + q4*8];
        }
        __syncthreads();
        #pragma unroll
        for (int ks = 0; ks < 4; ks++){
            u32 ah[4], al[4];
            ldsm4(ah[0],ah[1],ah[2],ah[3], a_h + ks*32);
            ldsm4(al[0],al[1],al[2],al[3], a_l + ks*32);
            #pragma unroll
            for (int ph = 0; ph < 2; ph++){
                u32 b0h[4], b1h[4], b0l[4], b1l[4];
                ldsm4(b0h[0],b0h[1],b0h[2],b0h[3], b_h + (2*ph)*2304   + ks*32);
                ldsm4(b1h[0],b1h[1],b1h[2],b1h[3], b_h + (2*ph+1)*2304 + ks*32);
                ldsm4(b0l[0],b0l[1],b0l[2],b0l[3], b_l + (2*ph)*2304   + ks*32);
                ldsm4(b1l[0],b1l[1],b1l[2],b1l[3], b_l + (2*ph+1)*2304 + ks*32);
                // 4 independent accumulators per group: dep distance 4
                mma_bf(acc[4*ph+0], ah, b0h[0], b0h[1]);
                mma_bf(acc[4*ph+1], ah, b0h[2], b0h[3]);
                mma_bf(acc[4*ph+2], ah, b1h[0], b1h[1]);
                mma_bf(acc[4*ph+3], ah, b1h[2], b1h[3]);
                mma_bf(acc[4*ph+0], ah, b0l[0], b0l[1]);
                mma_bf(acc[4*ph+1], ah, b0l[2], b0l[3]);
                mma_bf(acc[4*ph+2], ah, b1l[0], b1l[1]);
                mma_bf(acc[4*ph+3], ah, b1l[2], b1l[3]);
                mma_bf(acc[4*ph+0], al, b0h[0], b0h[1]);
                mma_bf(acc[4*ph+1], al, b0h[2], b0h[3]);
                mma_bf(acc[4*ph+2], al, b1h[0], b1h[1]);
                mma_bf(acc[4*ph+3], al, b1h[2], b1h[3]);
            }
        }
    }

    const int g = lane >> 2, t2 = lane & 3;
    const int r0 = m0 + 16*warp + g, r1 = r0 + 8;
    #pragma unroll
    for (int nb = 0; nb < 8; nb++){
        // acc idx mapping: group ph covers n-blocks 2*ph(+1) -> cols as before
        int col = nb*8 + t2*2;
        float b0v = bias[col], b1v = bias[col+1];
        float v00 = fmaxf(acc[nb][0] + b0v, 0.f);
        float v01 = fmaxf(acc[nb][1] + b1v, 0.f);
        float v10 = fmaxf(acc[nb][2] + b0v, 0.f);
        float v11 = fmaxf(acc[nb][3] + b1v, 0.f);
        if (w == 2){
            storeV(r0, col, v00); storeV(r0, col+1, v01);
            storeV(r1, col, v10); storeV(r1, col+1, v11);
        } else {
            u16* Oh = (w==0) ? g_Qh : g_Kh;
            u16* Ol = (w==0) ? g_Ql : g_Kl;
            u32 h = packbf(v00, v01);
            u32 lo = packbf(v00 - bflo(h), v01 - bfhi(h));
            *(u32*)&Oh[(size_t)r0*DH + col] = h; *(u32*)&Ol[(size_t)r0*DH + col] = lo;
            h = packbf(v10, v11);
            lo = packbf(v10 - bflo(h), v11 - bfhi(h));
            *(u32*)&Oh[(size_t)r1*DH + col] = h; *(u32*)&Ol[(size_t)r1*DH + col] = lo;
        }
    }
}

// ---------------- kernel: flash attention via MMA, KV-split ----------------
// grid (SS/64, BB, NSPLIT), 128 threads. Bq=64, Bk=64.
__global__ __launch_bounds__(128, 4) void attn_mma()
{
    extern __shared__ u16 smu[];
    u16* Qh = smu;
    u16* Ql = Qh + 4608;
    u16* Kh = Ql + 4608;
    u16* Kl = Kh + 4608;
    u16* Vh = Kl + 4608;
    u16* Vl = Vh + 4608;

    const int t = threadIdx.x, lane = t & 31, warp = t >> 5;
    const int b = blockIdx.y, z = blockIdx.z;
    const int q0 = blockIdx.x * 64;
    const int base = b * SS;

    #pragma unroll
    for (int u = 0; u < 4; u++){
        int idx = t + 128*u; int row = idx >> 3, q4 = idx & 7;
        *(uint4*)&Qh[row*72 + q4*8] = *(const uint4*)&g_Qh[(size_t)(base+q0+row)*DH + q4*8];
        *(uint4*)&Ql[row*72 + q4*8] = *(const uint4*)&g_Ql[(size_t)(base+q0+row)*DH + q4*8];
    }
    __syncthreads();

    const u32 aoff = ((16*warp + (lane&15))*72 + ((lane>>4)<<3)) * 2;
    const u32 boff = (((lane&7) + ((lane>>4)<<3))*72 + (((lane>>3)&1)<<3)) * 2;
    const u32 qh_a = smaddr(Qh) + aoff, ql_a = smaddr(Ql) + aoff;
    const u32 kh_b = smaddr(Kh) + boff, kl_b = smaddr(Kl) + boff;
    const u32 vh_b = smaddr(Vh) + boff, vl_b = smaddr(Vl) + boff;

    u32 qhf[4][4];
    #pragma unroll
    for (int ks = 0; ks < 4; ks++)
        ldsm4(qhf[ks][0],qhf[ks][1],qhf[ks][2],qhf[ks][3], qh_a + ks*32);

    float o[8][4] = {};
    float mr[2] = {-3e38f, -3e38f};
    float lr[2] = {0.f, 0.f};

    for (int it = 0; it < KT_PER; it++){
        const int k0 = (z*KT_PER + it) * 64;
        __syncthreads();
        #pragma unroll
        for (int u = 0; u < 4; u++){
            int idx = t + 128*u; int row = idx >> 3, q4 = idx & 7;
            *(uint4*)&Kh[row*72 + q4*8] = *(const uint4*)&g_Kh[(size_t)(base+k0+row)*DH + q4*8];
            *(uint4*)&Kl[row*72 + q4*8] = *(const uint4*)&g_Kl[(size_t)(base+k0+row)*DH + q4*8];
            *(uint4*)&Vh[row*72 + q4*8] = *(const uint4*)&g_Vh[(size_t)(b*64+row)*SS + k0 + q4*8];
            *(uint4*)&Vl[row*72 + q4*8] = *(const uint4*)&g_Vl[(size_t)(b*64+row)*SS + k0 + q4*8];
        }
        __syncthreads();

        // ---- S = Q @ K^T (split), grouped for dep distance 4 ----
        float s[8][4] = {};
        #pragma unroll
        for (int ks = 0; ks < 4; ks++){
            u32 qlf[4];
            ldsm4(qlf[0],qlf[1],qlf[2],qlf[3], ql_a + ks*32);
            #pragma unroll
            for (int ph = 0; ph < 2; ph++){
                u32 b0h[4], b1h[4], b0l[4], b1l[4];
                ldsm4(b0h[0],b0h[1],b0h[2],b0h[3], kh_b + (2*ph)*2304   + ks*32);
                ldsm4(b1h[0],b1h[1],b1h[2],b1h[3], kh_b + (2*ph+1)*2304 + ks*32);
                ldsm4(b0l[0],b0l[1],b0l[2],b0l[3], kl_b + (2*ph)*2304   + ks*32);
                ldsm4(b1l[0],b1l[1],b1l[2],b1l[3], kl_b + (2*ph+1)*2304 + ks*32);
                mma_bf(s[4*ph+0], qhf[ks], b0h[0], b0h[1]);
                mma_bf(s[4*ph+1], qhf[ks], b0h[2], b0h[3]);
                mma_bf(s[4*ph+2], qhf[ks], b1h[0], b1h[1]);
                mma_bf(s[4*ph+3], qhf[ks], b1h[2], b1h[3]);
                mma_bf(s[4*ph+0], qhf[ks], b0l[0], b0l[1]);
                mma_bf(s[4*ph+1], qhf[ks], b0l[2], b0l[3]);
                mma_bf(s[4*ph+2], qhf[ks], b1l[0], b1l[1]);
                mma_bf(s[4*ph+3], qhf[ks], b1l[2], b1l[3]);
                mma_bf(s[4*ph+0], qlf, b0h[0], b0h[1]);
                mma_bf(s[4*ph+1], qlf, b0h[2], b0h[3]);
                mma_bf(s[4*ph+2], qlf, b1h[0], b1h[1]);
                mma_bf(s[4*ph+3], qlf, b1h[2], b1h[3]);
            }
        }

        // ---- online softmax (rows g, g+8), quad-lane reductions ----
        // NOTE: s group mapping: s[4*ph+q] covers n-block (4*ph+q)... column
        // mapping is a pure permutation of n-blocks; softmax is row-wise and
        // PV uses the same permutation on V blocks, so it cancels — but we
        // keep the identity mapping by matching PV group order below.
        #pragma unroll
        for (int ri = 0; ri < 2; ri++){
            float mi = -3e38f;
            #pragma unroll
            for (int nb = 0; nb < 8; nb++)
                mi = fmaxf(mi, fmaxf(s[nb][2*ri], s[nb][2*ri+1]));
            mi = fmaxf(mi, __shfl_xor_sync(0xffffffffu, mi, 1));
            mi = fmaxf(mi, __shfl_xor_sync(0xffffffffu, mi, 2));
            float mnew = fmaxf(mr[ri], mi);
            float scl = __expf(mr[ri] - mnew);
            mr[ri] = mnew;
            float li = 0.f;
            #pragma unroll
            for (int nb = 0; nb < 8; nb++){
                float e0 = __expf(s[nb][2*ri]   - mnew);
                float e1 = __expf(s[nb][2*ri+1] - mnew);
                s[nb][2*ri] = e0; s[nb][2*ri+1] = e1;
                li += e0 + e1;
                o[nb][2*ri]   *= scl;
                o[nb][2*ri+1] *= scl;
            }
            li += __shfl_xor_sync(0xffffffffu, li, 1);
            li += __shfl_xor_sync(0xffffffffu, li, 2);
            lr[ri] = lr[ri]*scl + li;
        }

        // ---- P C-frag -> A-frag in registers (no shuffles), split ----
        // s[2*ks],s[2*ks+1] are the k-slices ks of P (same mapping as R4:
        // n-block index == 8*ks span) — unchanged since group order above
        // preserves nb ordering: 4*ph+q enumerates 0..7 in order.
        u32 ph4[4][4], pl4[4][4];
        #pragma unroll
        for (int ks = 0; ks < 4; ks++){
            ph4[ks][0] = packbf(s[2*ks][0],   s[2*ks][1]);
            ph4[ks][1] = packbf(s[2*ks][2],   s[2*ks][3]);
            ph4[ks][2] = packbf(s[2*ks+1][0], s[2*ks+1][1]);
            ph4[ks][3] = packbf(s[2*ks+1][2], s[2*ks+1][3]);
            pl4[ks][0] = packbf(s[2*ks][0]   - bflo(ph4[ks][0]), s[2*ks][1]   - bfhi(ph4[ks][0]));
            pl4[ks][1] = packbf(s[2*ks][2]   - bflo(ph4[ks][1]), s[2*ks][3]   - bfhi(ph4[ks][1]));
            pl4[ks][2] = packbf(s[2*ks+1][0] - bflo(ph4[ks][2]), s[2*ks+1][1] - bfhi(ph4[ks][2]));
            pl4[ks][3] = packbf(s[2*ks+1][2] - bflo(ph4[ks][3]), s[2*ks+1][3] - bfhi(ph4[ks][3]));
        }

        // ---- O += P @ V (split), grouped for dep distance 4 ----
        #pragma unroll
        for (int ks = 0; ks < 4; ks++){
            #pragma unroll
            for (int ph = 0; ph < 2; ph++){
                u32 v0h[4], v1h[4], v0l[4], v1l[4];
                ldsm4(v0h[0],v0h[1],v0h[2],v0h[3], vh_b + (2*ph)*2304   + ks*32);
                ldsm4(v1h[0],v1h[1],v1h[2],v1h[3], vh_b + (2*ph+1)*2304 + ks*32);
                ldsm4(v0l[0],v0l[1],v0l[2],v0l[3], vl_b + (2*ph)*2304   + ks*32);
                ldsm4(v1l[0],v1l[1],v1l[2],v1l[3], vl_b + (2*ph+1)*2304 + ks*32);
                mma_bf(o[4*ph+0], ph4[ks], v0h[0], v0h[1]);
                mma_bf(o[4*ph+1], ph4[ks], v0h[2], v0h[3]);
                mma_bf(o[4*ph+2], ph4[ks], v1h[0], v1h[1]);
                mma_bf(o[4*ph+3], ph4[ks], v1h[2], v1h[3]);
                mma_bf(o[4*ph+0], ph4[ks], v0l[0], v0l[1]);
                mma_bf(o[4*ph+1], ph4[ks], v0l[2], v0l[3]);
                mma_bf(o[4*ph+2], ph4[ks], v1l[0], v1l[1]);
                mma_bf(o[4*ph+3], ph4[ks], v1l[2], v1l[3]);
                mma_bf(o[4*ph+0], pl4[ks], v0h[0], v0h[1]);
                mma_bf(o[4*ph+1], pl4[ks], v0h[2], v0h[3]);
                mma_bf(o[4*ph+2], pl4[ks], v1h[0], v1h[1]);
                mma_bf(o[4*ph+3], pl4[ks], v1h[2], v1h[3]);
            }
        }
    }

    // write unnormalized partials + stats
    const int g = lane >> 2, t2 = lane & 3;
    const int r0 = base + q0 + 16*warp + g, r1 = r0 + 8;
    #pragma unroll
    for (int nb = 0; nb < 8; nb++){
        *(float2*)&g_Op[z][(size_t)r0*DH + nb*8 + t2*2] = make_float2(o[nb][0], o[nb][1]);
        *(float2*)&g_Op[z][(size_t)r1*DH + nb*8 + t2*2] = make_float2(o[nb][2], o[nb][3]);
    }
    if (t2 == 0){
        g_m[z][r0] = mr[0]; g_l[z][r0] = lr[0];
        g_m[z][r1] = mr[1]; g_l[z][r1] = lr[1];
    }
}

// ---------------- kernel: flash split combine + mask -----------------------
__global__ __launch_bounds__(256) void combine(const float* __restrict__ mask,
                                               float* __restrict__ out){
    int idx = blockIdx.x*256 + threadIdx.x;   // row*16 + dquad
    int row = idx >> 4, dq = idx & 15;
    float mm = -3e38f;
    #pragma unroll
    for (int z = 0; z < NSPLIT; z++) mm = fmaxf(mm, g_m[z][row]);
    float den = 0.f;
    float4 r = make_float4(0.f, 0.f, 0.f, 0.f);
    #pragma unroll
    for (int z = 0; z < NSPLIT; z++){
        float wz = __expf(g_m[z][row] - mm);
        den += wz * g_l[z][row];
        float4 a = *(const float4*)&g_Op[z][(size_t)row*DH + dq*4];
        r.x += a.x*wz; r.y += a.y*wz; r.z += a.z*wz; r.w += a.w*wz;
    }
    float f = mask[row] / den;
    r.x *= f; r.y *= f; r.z *= f; r.w *= f;
    *(float4*)&out[(size_t)row*DH + dq*4] = r;
}

// ---------------------------------------------------------------------------
extern "C" void kernel_launch(void* const* d_in, const int* in_sizes, int n_in,
                              void* d_out, int out_size)
{
    const float* X    = (const float*)d_in[0];
    const float* mask = (const float*)d_in[1];
    const float* Wq   = (const float*)d_in[2];
    const float* bq   = (const float*)d_in[3];
    const float* Wk   = (const float*)d_in[4];
    const float* bk   = (const float*)d_in[5];
    const float* Wv   = (const float*)d_in[6];
    const float* bv   = (const float*)d_in[7];

    const int smem_attn = 6 * 64 * 72 * (int)sizeof(u16);  // 55296 B
    cudaFuncSetAttribute(attn_mma,
                         cudaFuncAttributeMaxDynamicSharedMemorySize, smem_attn);

    cvt_x<<<MROWS*DIN/4/256, 256>>>(X);
    cvt_w<<<3*DH*DIN/256, 256>>>(Wq, Wk, Wv);
    qkv_mma<<<dim3(MROWS/64, 3), 128>>>(bq, bk, bv);
    attn_mma<<<dim3(SS/64, BB, NSPLIT), 128, smem_attn>>>();
    combine<<<MROWS*DH/4/256, 256>>>(mask, (float*)d_out);
}

// round 9
// speedup vs baseline: 1.3634x; 1.0418x over previous
#include <cuda_runtime.h>

typedef unsigned int u32;
typedef unsigned short u16;

#define BB 4
#define SS 4096
#define DIN 1024
#define DH 64
#define MROWS (BB*SS)
#define NSPLIT 8
#define KTS (SS/64)
#define KT_PER (KTS/NSPLIT)

// ---------------- scratch (static device memory; no allocations) ----------
__device__ u16 g_Xh[MROWS*DIN], g_Xl[MROWS*DIN];           // X split bf16
__device__ u16 g_Wth[3][DH*DIN], g_Wtl[3][DH*DIN];         // W^T split bf16 [out][din]
__device__ u16 g_Qh[MROWS*DH], g_Ql[MROWS*DH];             // [row][d]
__device__ u16 g_Kh[MROWS*DH], g_Kl[MROWS*DH];             // [row][d]
__device__ u16 g_Vh[MROWS*DH], g_Vl[MROWS*DH];             // transposed [b][d][s]
__device__ float g_Op[NSPLIT][MROWS*DH];                   // unnormalized partial O
__device__ float g_m[NSPLIT][MROWS];
__device__ float g_l[NSPLIT][MROWS];

// ---------------- helpers --------------------------------------------------
__device__ __forceinline__ u32 packbf(float lo, float hi){
    u32 r; asm("cvt.rn.bf16x2.f32 %0, %1, %2;" : "=r"(r) : "f"(hi), "f"(lo)); return r;
}
__device__ __forceinline__ float bflo(u32 p){ return __uint_as_float(p << 16); }
__device__ __forceinline__ float bfhi(u32 p){ return __uint_as_float(p & 0xffff0000u); }
__device__ __forceinline__ u32 smaddr(const void* p){ return (u32)__cvta_generic_to_shared(p); }

__device__ __forceinline__ void ldsm4(u32& r0,u32& r1,u32& r2,u32& r3, u32 a){
    asm volatile("ldmatrix.sync.aligned.m8n8.x4.shared.b16 {%0,%1,%2,%3}, [%4];"
        : "=r"(r0),"=r"(r1),"=r"(r2),"=r"(r3) : "r"(a));
}
__device__ __forceinline__ void mma_bf(float* c, const u32* a, u32 b0, u32 b1){
    asm volatile("mma.sync.aligned.m16n8k16.row.col.f32.bf16.bf16.f32 "
        "{%0,%1,%2,%3},{%4,%5,%6,%7},{%8,%9},{%0,%1,%2,%3};"
        : "+f"(c[0]),"+f"(c[1]),"+f"(c[2]),"+f"(c[3])
        : "r"(a[0]),"r"(a[1]),"r"(a[2]),"r"(a[3]),"r"(b0),"r"(b1));
}

// ---------------- kernel: convert X to split bf16 --------------------------
__global__ __launch_bounds__(256) void cvt_x(const float* __restrict__ X){
    size_t i = (size_t)(blockIdx.x*256 + threadIdx.x) * 4;
    float4 v = *(const float4*)&X[i];
    u32 h01 = packbf(v.x, v.y), h23 = packbf(v.z, v.w);
    u32 l01 = packbf(v.x - bflo(h01), v.y - bfhi(h01));
    u32 l23 = packbf(v.z - bflo(h23), v.w - bfhi(h23));
    *(uint2*)&g_Xh[i] = make_uint2(h01, h23);
    *(uint2*)&g_Xl[i] = make_uint2(l01, l23);
}

// ---------------- kernel: convert+transpose weights ------------------------
__global__ __launch_bounds__(256) void cvt_w(const float* __restrict__ Wq,
                                             const float* __restrict__ Wk,
                                             const float* __restrict__ Wv){
    int id = blockIdx.x*256 + threadIdx.x;
    int w = id >> 16; int r = id & 65535;
    int n = r >> 10, k = r & 1023;
    const float* W = (w==0) ? Wq : (w==1) ? Wk : Wv;
    float x = W[k*DH + n];
    u32 p = packbf(x, 0.f);
    u32 q = packbf(x - bflo(p), 0.f);
    g_Wth[w][n*DIN + k] = (u16)(p & 0xffff);
    g_Wtl[w][n*DIN + k] = (u16)(q & 0xffff);
}

__device__ __forceinline__ void storeV(int r, int c, float v){
    int bb = r >> 12, s = r & 4095;
    u32 p = packbf(v, 0.f);
    g_Vh[(size_t)(bb*64 + c)*SS + s] = (u16)(p & 0xffff);
    u32 q = packbf(v - bflo(p), 0.f);
    g_Vl[(size_t)(bb*64 + c)*SS + s] = (u16)(q & 0xffff);
}

// ---------------- kernel: QKV projection via HMMA (unchanged, R7) ----------
__global__ __launch_bounds__(128, 4) void qkv_mma(
    const float* __restrict__ bq, const float* __restrict__ bk,
    const float* __restrict__ bv)
{
    __shared__ u16 Xs_h[64*72], Xs_l[64*72], Ws_h[64*72], Ws_l[64*72];
    const int t = threadIdx.x, lane = t & 31, warp = t >> 5;
    const int w = blockIdx.y;
    const int m0 = blockIdx.x * 64;
    const u16* Wth = g_Wth[w]; const u16* Wtl = g_Wtl[w];
    const float* bias = (w==0) ? bq : (w==1) ? bk : bv;

    const u32 aoff = ((16*warp + (lane&15))*72 + ((lane>>4)<<3)) * 2;
    const u32 boff = (((lane&7) + ((lane>>4)<<3))*72 + (((lane>>3)&1)<<3)) * 2;
    const u32 a_h = smaddr(Xs_h) + aoff, a_l = smaddr(Xs_l) + aoff;
    const u32 b_h = smaddr(Ws_h) + boff, b_l = smaddr(Ws_l) + boff;

    float acc[8][4] = {};
    for (int c16 = 0; c16 < 16; c16++){
        __syncthreads();
        #pragma unroll
        for (int u = 0; u < 4; u++){
            int idx = t + 128*u; int row = idx >> 3, q4 = idx & 7;
            *(uint4*)&Xs_h[row*72 + q4*8] = *(const uint4*)&g_Xh[(size_t)(m0+row)*DIN + c16*64 + q4*8];
            *(uint4*)&Xs_l[row*72 + q4*8] = *(const uint4*)&g_Xl[(size_t)(m0+row)*DIN + c16*64 + q4*8];
            *(uint4*)&Ws_h[row*72 + q4*8] = *(const uint4*)&Wth[(size_t)row*DIN + c16*64 + q4*8];
            *(uint4*)&Ws_l[row*72 + q4*8] = *(const uint4*)&Wtl[(size_t)row*DIN + c16*64 + q4*8];
        }
        __syncthreads();
        #pragma unroll
        for (int ks = 0; ks < 4; ks++){
            u32 ah[4], al[4];
            ldsm4(ah[0],ah[1],ah[2],ah[3], a_h + ks*32);
            ldsm4(al[0],al[1],al[2],al[3], a_l + ks*32);
            #pragma unroll
            for (int ph = 0; ph < 2; ph++){
                u32 b0h[4], b1h[4], b0l[4], b1l[4];
                ldsm4(b0h[0],b0h[1],b0h[2],b0h[3], b_h + (2*ph)*2304   + ks*32);
                ldsm4(b1h[0],b1h[1],b1h[2],b1h[3], b_h + (2*ph+1)*2304 + ks*32);
                ldsm4(b0l[0],b0l[1],b0l[2],b0l[3], b_l + (2*ph)*2304   + ks*32);
                ldsm4(b1l[0],b1l[1],b1l[2],b1l[3], b_l + (2*ph+1)*2304 + ks*32);
                mma_bf(acc[4*ph+0], ah, b0h[0], b0h[1]);
                mma_bf(acc[4*ph+1], ah, b0h[2], b0h[3]);
                mma_bf(acc[4*ph+2], ah, b1h[0], b1h[1]);
                mma_bf(acc[4*ph+3], ah, b1h[2], b1h[3]);
                mma_bf(acc[4*ph+0], ah, b0l[0], b0l[1]);
                mma_bf(acc[4*ph+1], ah, b0l[2], b0l[3]);
                mma_bf(acc[4*ph+2], ah, b1l[0], b1l[1]);
                mma_bf(acc[4*ph+3], ah, b1l[2], b1l[3]);
                mma_bf(acc[4*ph+0], al, b0h[0], b0h[1]);
                mma_bf(acc[4*ph+1], al, b0h[2], b0h[3]);
                mma_bf(acc[4*ph+2], al, b1h[0], b1h[1]);
                mma_bf(acc[4*ph+3], al, b1h[2], b1h[3]);
            }
        }
    }

    const int g = lane >> 2, t2 = lane & 3;
    const int r0 = m0 + 16*warp + g, r1 = r0 + 8;
    #pragma unroll
    for (int nb = 0; nb < 8; nb++){
        int col = nb*8 + t2*2;
        float b0v = bias[col], b1v = bias[col+1];
        float v00 = fmaxf(acc[nb][0] + b0v, 0.f);
        float v01 = fmaxf(acc[nb][1] + b1v, 0.f);
        float v10 = fmaxf(acc[nb][2] + b0v, 0.f);
        float v11 = fmaxf(acc[nb][3] + b1v, 0.f);
        if (w == 2){
            storeV(r0, col, v00); storeV(r0, col+1, v01);
            storeV(r1, col, v10); storeV(r1, col+1, v11);
        } else {
            u16* Oh = (w==0) ? g_Qh : g_Kh;
            u16* Ol = (w==0) ? g_Ql : g_Kl;
            u32 h = packbf(v00, v01);
            u32 lo = packbf(v00 - bflo(h), v01 - bfhi(h));
            *(u32*)&Oh[(size_t)r0*DH + col] = h; *(u32*)&Ol[(size_t)r0*DH + col] = lo;
            h = packbf(v10, v11);
            lo = packbf(v10 - bflo(h), v11 - bfhi(h));
            *(u32*)&Oh[(size_t)r1*DH + col] = h; *(u32*)&Ol[(size_t)r1*DH + col] = lo;
        }
    }
}

// ---------------- kernel: flash attention via HMMA, M=32/warp --------------
// grid (SS/128, BB, NSPLIT), 128 threads. Bq=128 (4 warps x 32 rows), Bk=64.
// Each warp owns 2 m16 row-groups; B fragments amortized over both.
__global__ __launch_bounds__(128, 2) void attn_mma()
{
    extern __shared__ u16 smu[];
    u16* Qh = smu;                 // 128*72
    u16* Ql = Qh + 128*72;
    u16* Kh = Ql + 128*72;         // 64*72 each below
    u16* Kl = Kh + 64*72;
    u16* Vh = Kl + 64*72;
    u16* Vl = Vh + 64*72;

    const int t = threadIdx.x, lane = t & 31, wid = t >> 5;
    const int b = blockIdx.y, z = blockIdx.z;
    const int q0 = blockIdx.x * 128;
    const int base = b * SS;

    // stage Q (128 rows, hi+lo)
    #pragma unroll
    for (int u = 0; u < 8; u++){
        int idx = t + 128*u; int row = idx >> 3, q4 = idx & 7;
        *(uint4*)&Qh[row*72 + q4*8] = *(const uint4*)&g_Qh[(size_t)(base+q0+row)*DH + q4*8];
        *(uint4*)&Ql[row*72 + q4*8] = *(const uint4*)&g_Ql[(size_t)(base+q0+row)*DH + q4*8];
    }

    // A-operand smem addrs for the warp's two 16-row groups
    u32 qh_a[2], ql_a[2];
    #pragma unroll
    for (int grp = 0; grp < 2; grp++){
        u32 aoff = ((u32)(32*wid + 16*grp + (lane&15))*72 + ((lane>>4)<<3)) * 2;
        qh_a[grp] = smaddr(Qh) + aoff;
        ql_a[grp] = smaddr(Ql) + aoff;
    }
    const u32 boff = (((lane&7) + ((lane>>4)<<3))*72 + (((lane>>3)&1)<<3)) * 2;
    const u32 kh_b = smaddr(Kh) + boff, kl_b = smaddr(Kl) + boff;
    const u32 vh_b = smaddr(Vh) + boff, vl_b = smaddr(Vl) + boff;

    float o[2][8][4] = {};
    float mr[2][2] = {{-3e38f,-3e38f},{-3e38f,-3e38f}};
    float lr[2][2] = {{0.f,0.f},{0.f,0.f}};

    for (int it = 0; it < KT_PER; it++){
        const int k0 = (z*KT_PER + it) * 64;
        __syncthreads();
        #pragma unroll
        for (int u = 0; u < 4; u++){
            int idx = t + 128*u; int row = idx >> 3, q4 = idx & 7;
            *(uint4*)&Kh[row*72 + q4*8] = *(const uint4*)&g_Kh[(size_t)(base+k0+row)*DH + q4*8];
            *(uint4*)&Kl[row*72 + q4*8] = *(const uint4*)&g_Kl[(size_t)(base+k0+row)*DH + q4*8];
            *(uint4*)&Vh[row*72 + q4*8] = *(const uint4*)&g_Vh[(size_t)(b*64+row)*SS + k0 + q4*8];
            *(uint4*)&Vl[row*72 + q4*8] = *(const uint4*)&g_Vl[(size_t)(b*64+row)*SS + k0 + q4*8];
        }
        __syncthreads();

        // ---- S = Q @ K^T (split), both row groups share B frags ----
        float s[2][8][4] = {};
        #pragma unroll
        for (int ks = 0; ks < 4; ks++){
            u32 ah[2][4], al[2][4];
            #pragma unroll
            for (int grp = 0; grp < 2; grp++){
                ldsm4(ah[grp][0],ah[grp][1],ah[grp][2],ah[grp][3], qh_a[grp] + ks*32);
                ldsm4(al[grp][0],al[grp][1],al[grp][2],al[grp][3], ql_a[grp] + ks*32);
            }
            #pragma unroll
            for (int ph = 0; ph < 2; ph++){
                u32 b0h[4], b1h[4], b0l[4], b1l[4];
                ldsm4(b0h[0],b0h[1],b0h[2],b0h[3], kh_b + (2*ph)*2304   + ks*32);
                ldsm4(b1h[0],b1h[1],b1h[2],b1h[3], kh_b + (2*ph+1)*2304 + ks*32);
                ldsm4(b0l[0],b0l[1],b0l[2],b0l[3], kl_b + (2*ph)*2304   + ks*32);
                ldsm4(b1l[0],b1l[1],b1l[2],b1l[3], kl_b + (2*ph+1)*2304 + ks*32);
                #pragma unroll
                for (int grp = 0; grp < 2; grp++){
                    mma_bf(s[grp][4*ph+0], ah[grp], b0h[0], b0h[1]);
                    mma_bf(s[grp][4*ph+1], ah[grp], b0h[2], b0h[3]);
                    mma_bf(s[grp][4*ph+2], ah[grp], b1h[0], b1h[1]);
                    mma_bf(s[grp][4*ph+3], ah[grp], b1h[2], b1h[3]);
                    mma_bf(s[grp][4*ph+0], ah[grp], b0l[0], b0l[1]);
                    mma_bf(s[grp][4*ph+1], ah[grp], b0l[2], b0l[3]);
                    mma_bf(s[grp][4*ph+2], ah[grp], b1l[0], b1l[1]);
                    mma_bf(s[grp][4*ph+3], ah[grp], b1l[2], b1l[3]);
                    mma_bf(s[grp][4*ph+0], al[grp], b0h[0], b0h[1]);
                    mma_bf(s[grp][4*ph+1], al[grp], b0h[2], b0h[3]);
                    mma_bf(s[grp][4*ph+2], al[grp], b1h[0], b1h[1]);
                    mma_bf(s[grp][4*ph+3], al[grp], b1h[2], b1h[3]);
                }
            }
        }

        // ---- online softmax (4 rows/thread: grp x {g, g+8}) ----
        float scl[2][2];
        #pragma unroll
        for (int grp = 0; grp < 2; grp++){
            #pragma unroll
            for (int ri = 0; ri < 2; ri++){
                float mi = -3e38f;
                #pragma unroll
                for (int nb = 0; nb < 8; nb++)
                    mi = fmaxf(mi, fmaxf(s[grp][nb][2*ri], s[grp][nb][2*ri+1]));
                mi = fmaxf(mi, __shfl_xor_sync(0xffffffffu, mi, 1));
                mi = fmaxf(mi, __shfl_xor_sync(0xffffffffu, mi, 2));
                float mnew = fmaxf(mr[grp][ri], mi);
                float sc = __expf(mr[grp][ri] - mnew);
                scl[grp][ri] = sc;
                mr[grp][ri] = mnew;
                float li = 0.f;
                #pragma unroll
                for (int nb = 0; nb < 8; nb++){
                    float e0 = __expf(s[grp][nb][2*ri]   - mnew);
                    float e1 = __expf(s[grp][nb][2*ri+1] - mnew);
                    s[grp][nb][2*ri] = e0; s[grp][nb][2*ri+1] = e1;
                    li += e0 + e1;
                    o[grp][nb][2*ri]   *= sc;
                    o[grp][nb][2*ri+1] *= sc;
                }
                li += __shfl_xor_sync(0xffffffffu, li, 1);
                li += __shfl_xor_sync(0xffffffffu, li, 2);
                lr[grp][ri] = lr[grp][ri]*sc + li;
            }
        }

        // ---- P convert (per ks, in place) + O += P @ V (shared V frags) ----
        #pragma unroll
        for (int ks = 0; ks < 4; ks++){
            u32 ph4[2][4], pl4[2][4];
            #pragma unroll
            for (int grp = 0; grp < 2; grp++){
                ph4[grp][0] = packbf(s[grp][2*ks][0],   s[grp][2*ks][1]);
                ph4[grp][1] = packbf(s[grp][2*ks][2],   s[grp][2*ks][3]);
                ph4[grp][2] = packbf(s[grp][2*ks+1][0], s[grp][2*ks+1][1]);
                ph4[grp][3] = packbf(s[grp][2*ks+1][2], s[grp][2*ks+1][3]);
                pl4[grp][0] = packbf(s[grp][2*ks][0]   - bflo(ph4[grp][0]), s[grp][2*ks][1]   - bfhi(ph4[grp][0]));
                pl4[grp][1] = packbf(s[grp][2*ks][2]   - bflo(ph4[grp][1]), s[grp][2*ks][3]   - bfhi(ph4[grp][1]));
                pl4[grp][2] = packbf(s[grp][2*ks+1][0] - bflo(ph4[grp][2]), s[grp][2*ks+1][1] - bfhi(ph4[grp][2]));
                pl4[grp][3] = packbf(s[grp][2*ks+1][2] - bflo(ph4[grp][3]), s[grp][2*ks+1][3] - bfhi(ph4[grp][3]));
            }
            #pragma unroll
            for (int ph = 0; ph < 2; ph++){
                u32 v0h[4], v1h[4], v0l[4], v1l[4];
                ldsm4(v0h[0],v0h[1],v0h[2],v0h[3], vh_b + (2*ph)*2304   + ks*32);
                ldsm4(v1h[0],v1h[1],v1h[2],v1h[3], vh_b + (2*ph+1)*2304 + ks*32);
                ldsm4(v0l[0],v0l[1],v0l[2],v0l[3], vl_b + (2*ph)*2304   + ks*32);
                ldsm4(v1l[0],v1l[1],v1l[2],v1l[3], vl_b + (2*ph+1)*2304 + ks*32);
                #pragma unroll
                for (int grp = 0; grp < 2; grp++){
                    mma_bf(o[grp][4*ph+0], ph4[grp], v0h[0], v0h[1]);
                    mma_bf(o[grp][4*ph+1], ph4[grp], v0h[2], v0h[3]);
                    mma_bf(o[grp][4*ph+2], ph4[grp], v1h[0], v1h[1]);
                    mma_bf(o[grp][4*ph+3], ph4[grp], v1h[2], v1h[3]);
                    mma_bf(o[grp][4*ph+0], ph4[grp], v0l[0], v0l[1]);
                    mma_bf(o[grp][4*ph+1], ph4[grp], v0l[2], v0l[3]);
                    mma_bf(o[grp][4*ph+2], ph4[grp], v1l[0], v1l[1]);
                    mma_bf(o[grp][4*ph+3], ph4[grp], v1l[2], v1l[3]);
                    mma_bf(o[grp][4*ph+0], pl4[grp], v0h[0], v0h[1]);
                    mma_bf(o[grp][4*ph+1], pl4[grp], v0h[2], v0h[3]);
                    mma_bf(o[grp][4*ph+2], pl4[grp], v1h[0], v1h[1]);
                    mma_bf(o[grp][4*ph+3], pl4[grp], v1h[2], v1h[3]);
                }
            }
        }
    }

    // ---- write unnormalized partials + stats ----
    const int g = lane >> 2, t2 = lane & 3;
    #pragma unroll
    for (int grp = 0; grp < 2; grp++){
        const int r0 = base + q0 + 32*wid + 16*grp + g, r1 = r0 + 8;
        #pragma unroll
        for (int nb = 0; nb < 8; nb++){
            *(float2*)&g_Op[z][(size_t)r0*DH + nb*8 + t2*2] = make_float2(o[grp][nb][0], o[grp][nb][1]);
            *(float2*)&g_Op[z][(size_t)r1*DH + nb*8 + t2*2] = make_float2(o[grp][nb][2], o[grp][nb][3]);
        }
        if (t2 == 0){
            g_m[z][r0] = mr[grp][0]; g_l[z][r0] = lr[grp][0];
            g_m[z][r1] = mr[grp][1]; g_l[z][r1] = lr[grp][1];
        }
    }
}

// ---------------- kernel: flash split combine + mask -----------------------
__global__ __launch_bounds__(256) void combine(const float* __restrict__ mask,
                                               float* __restrict__ out){
    int idx = blockIdx.x*256 + threadIdx.x;   // row*16 + dquad
    int row = idx >> 4, dq = idx & 15;
    float mm = -3e38f;
    #pragma unroll
    for (int z = 0; z < NSPLIT; z++) mm = fmaxf(mm, g_m[z][row]);
    float den = 0.f;
    float4 r = make_float4(0.f, 0.f, 0.f, 0.f);
    #pragma unroll
    for (int z = 0; z < NSPLIT; z++){
        float wz = __expf(g_m[z][row] - mm);
        den += wz * g_l[z][row];
        float4 a = *(const float4*)&g_Op[z][(size_t)row*DH + dq*4];
        r.x += a.x*wz; r.y += a.y*wz; r.z += a.z*wz; r.w += a.w*wz;
    }
    float f = mask[row] / den;
    r.x *= f; r.y *= f; r.z *= f; r.w *= f;
    *(float4*)&out[(size_t)row*DH + dq*4] = r;
}

// ---------------------------------------------------------------------------
extern "C" void kernel_launch(void* const* d_in, const int* in_sizes, int n_in,
                              void* d_out, int out_size)
{
    const float* X    = (const float*)d_in[0];
    const float* mask = (const float*)d_in[1];
    const float* Wq   = (const float*)d_in[2];
    const float* bq   = (const float*)d_in[3];
    const float* Wk   = (const float*)d_in[4];
    const float* bk   = (const float*)d_in[5];
    const float* Wv   = (const float*)d_in[6];
    const float* bv   = (const float*)d_in[7];

    // smem: Qh+Ql (128x72 each) + Kh,Kl,Vh,Vl (64x72 each), u16
    const int smem_attn = (2*128*72 + 4*64*72) * (int)sizeof(u16);  // 73728 B
    cudaFuncSetAttribute(attn_mma,
                         cudaFuncAttributeMaxDynamicSharedMemorySize, smem_attn);

    cvt_x<<<MROWS*DIN/4/256, 256>>>(X);
    cvt_w<<<3*DH*DIN/256, 256>>>(Wq, Wk, Wv);
    qkv_mma<<<dim3(MROWS/64, 3), 128>>>(bq, bk, bv);
    attn_mma<<<dim3(SS/128, BB, NSPLIT), 128, smem_attn>>>();
    combine<<<MROWS*DH/4/256, 256>>>(mask, (float*)d_out);
}